// round 1
// baseline (speedup 1.0000x reference)
#include <cuda_runtime.h>

#define N_NODES 100000
#define N_EDGES 1600000
#define IN_DIM 512
#define H0 32
#define H1 8

// ---------------- scratch (static device globals; no allocation) ----------------
__device__ float g_xw[N_NODES * H0];    // x @ W0
__device__ float g_agg1[N_NODES * H0];  // conv1 neighbor accumulation
__device__ float g_deg[N_NODES];        // deg -> dinv (in place)
__device__ float g_deg2[N_NODES];       // deg2 -> dinv2 (in place)
__device__ int   g_row[N_EDGES];
__device__ int   g_col[N_EDGES];
__device__ float g_mw[N_EDGES];         // masked edge weights
__device__ float g_a1[N_NODES];
__device__ float g_a2[N_NODES];
__device__ float g_hw[N_NODES * H1];    // h @ W1
__device__ float g_wa1[H0];
__device__ float g_wa2[H0];
__device__ float g_c0;
__device__ int   g_is64;

// vector float atomic (sm_90+)
__device__ __forceinline__ void red_add_v4(float4* addr, float4 v) {
    asm volatile("red.global.add.v4.f32 [%0], {%1,%2,%3,%4};"
                 :: "l"(addr), "f"(v.x), "f"(v.y), "f"(v.z), "f"(v.w)
                 : "memory");
}

// ---------------- K0: init + tiny precomputes + dtype detection ----------------
__global__ void k_init(const void* __restrict__ edge_raw,
                       const float* __restrict__ Wnb, const float* __restrict__ bnb,
                       const float* __restrict__ Wself, const float* __restrict__ bself,
                       const float* __restrict__ Watt, const float* __restrict__ batt,
                       float* __restrict__ out, int N) {
    int i = blockIdx.x * blockDim.x + threadIdx.x;
    if (i < N * H0) g_agg1[i] = 0.f;
    if (i < N * H1) out[i] = 0.f;
    if (i < N) { g_deg[i] = 1.f; g_deg2[i] = 1.f; }
    if (blockIdx.x == 0) {
        if (threadIdx.x < H0) {
            int k = threadIdx.x;
            float s1 = 0.f, s2 = 0.f;
            #pragma unroll
            for (int j = 0; j < 8; j++) {
                s1 += Wnb[k * 8 + j] * Watt[j];
                s2 += Wself[k * 8 + j] * Watt[8 + j];
            }
            g_wa1[k] = s1; g_wa2[k] = s2;
        }
        if (threadIdx.x == 0) {
            float c = batt[0];
            #pragma unroll
            for (int j = 0; j < 8; j++) c += bnb[j] * Watt[j] + bself[j] * Watt[8 + j];
            g_c0 = c;
            // int64 vs int32 edge storage: int64 little-endian high words are 0
            const int* p = (const int*)edge_raw;
            int is64 = 1;
            for (int s = 1; s < 128; s += 2) if (p[s] != 0) { is64 = 0; break; }
            g_is64 = is64;
        }
    }
}

// ---------------- K1: edge index convert + degree count ----------------
__global__ void k_convert(const void* __restrict__ edge_raw, int E) {
    int e = blockIdx.x * blockDim.x + threadIdx.x;
    if (e >= E) return;
    int r, c;
    if (g_is64) {
        const long long* p = (const long long*)edge_raw;
        r = (int)p[e]; c = (int)p[E + e];
    } else {
        const int* p = (const int*)edge_raw;
        r = p[e]; c = p[E + e];
    }
    g_row[e] = r; g_col[e] = c;
    atomicAdd(&g_deg[c], 1.0f);
}

// ---------------- K2: xw = x @ W0 (fp32 tiled) ----------------
// tile: 128 rows x 32 cols, K-chunks of 32; 128 threads, 8x4 microtile each
__global__ void __launch_bounds__(128) k_gemm_xw(const float* __restrict__ x,
                                                 const float* __restrict__ W0, int N) {
    __shared__ float sX[32][128];  // transposed x chunk: sX[kk][r]
    __shared__ float sW[32][32];   // W0 chunk: sW[kk][c]
    int t = threadIdx.x;
    int row0 = blockIdx.x * 128;
    int rid = t >> 3;      // 0..15 -> rows rid*8..rid*8+7
    int cid = t & 7;       // 0..7  -> cols cid*4..cid*4+3
    float acc[8][4];
    #pragma unroll
    for (int i = 0; i < 8; i++)
        #pragma unroll
        for (int j = 0; j < 4; j++) acc[i][j] = 0.f;

    for (int kc = 0; kc < IN_DIM; kc += 32) {
        // W0 chunk: rows kc..kc+31 are contiguous (1024 floats)
        const float4* w4 = (const float4*)(W0 + kc * H0);
        float4* s4 = (float4*)&sW[0][0];
        s4[t] = w4[t];
        s4[t + 128] = w4[t + 128];
        // x chunk, transposed into smem
        int lr = t >> 3;
        int kg = (t & 7) * 4;
        #pragma unroll
        for (int it = 0; it < 8; it++) {
            int r = lr + it * 16;
            int grow = row0 + r;
            float4 v = make_float4(0.f, 0.f, 0.f, 0.f);
            if (grow < N) v = *(const float4*)&x[(size_t)grow * IN_DIM + kc + kg];
            sX[kg + 0][r] = v.x; sX[kg + 1][r] = v.y;
            sX[kg + 2][r] = v.z; sX[kg + 3][r] = v.w;
        }
        __syncthreads();
        #pragma unroll 8
        for (int kk = 0; kk < 32; kk++) {
            float4 wv = *(float4*)&sW[kk][cid * 4];
            float4 xa = *(float4*)&sX[kk][rid * 8];
            float4 xb = *(float4*)&sX[kk][rid * 8 + 4];
            float ax[8] = {xa.x, xa.y, xa.z, xa.w, xb.x, xb.y, xb.z, xb.w};
            float wc[4] = {wv.x, wv.y, wv.z, wv.w};
            #pragma unroll
            for (int i = 0; i < 8; i++)
                #pragma unroll
                for (int j = 0; j < 4; j++)
                    acc[i][j] = fmaf(ax[i], wc[j], acc[i][j]);
        }
        __syncthreads();
    }
    #pragma unroll
    for (int i = 0; i < 8; i++) {
        int grow = row0 + rid * 8 + i;
        if (grow < N) {
            float4 v = make_float4(acc[i][0], acc[i][1], acc[i][2], acc[i][3]);
            *(float4*)&g_xw[grow * H0 + cid * 4] = v;
        }
    }
}

// ---------------- K3: in-place rsqrt ----------------
__global__ void k_rsqrt(float* __restrict__ p, int N) {
    int i = blockIdx.x * blockDim.x + threadIdx.x;
    if (i < N) p[i] = rsqrtf(p[i]);
}

// ---------------- K4: conv1 aggregation (8 lanes/edge, float4 RED) ----------------
__global__ void __launch_bounds__(256) k_conv1_agg(int E) {
    int t = blockIdx.x * blockDim.x + threadIdx.x;
    int e = t >> 3;
    if (e >= E) return;
    int j = t & 7;
    int r = g_row[e], c = g_col[e];
    float norm = g_deg[r] * g_deg[c];  // dinv[r]*dinv[c]
    float4 v = ((const float4*)g_xw)[r * 8 + j];
    v.x *= norm; v.y *= norm; v.z *= norm; v.w *= norm;
    red_add_v4(&((float4*)g_agg1)[c * 8 + j], v);
}

// ---------------- K5: per-node finalize + attention scalars + hw = h@W1 ----------------
__global__ void __launch_bounds__(256) k_node(const float* __restrict__ b0,
                                              const float* __restrict__ W1, int N) {
    int warp = (blockIdx.x * blockDim.x + threadIdx.x) >> 5;
    int lane = threadIdx.x & 31;
    if (warp >= N) return;
    int n = warp;
    float di = g_deg[n];  // dinv
    float h = g_agg1[n * H0 + lane] + g_xw[n * H0 + lane] * di * di + b0[lane];
    float v1 = h * g_wa1[lane];
    float v2 = h * g_wa2[lane];
    #pragma unroll
    for (int o = 16; o; o >>= 1) {
        v1 += __shfl_xor_sync(0xffffffffu, v1, o);
        v2 += __shfl_xor_sync(0xffffffffu, v2, o);
    }
    if (lane == 0) { g_a1[n] = v1; g_a2[n] = v2; }
    #pragma unroll
    for (int j = 0; j < H1; j++) {
        float p = h * W1[lane * H1 + j];
        #pragma unroll
        for (int o = 16; o; o >>= 1) p += __shfl_xor_sync(0xffffffffu, p, o);
        if (lane == 0) g_hw[n * H1 + j] = p;
    }
}

// ---------------- K6: edge gate + masked weight + deg2 ----------------
__global__ void k_edge_gate(int E) {
    int e = blockIdx.x * blockDim.x + threadIdx.x;
    if (e >= E) return;
    int r = g_row[e], c = g_col[e];
    float w = g_a1[r] + g_a2[c] + g_c0;
    float mw = 0.f;
    if (w > 0.f) {
        float mask = fminf(1.01f / (1.f + __expf(-w)), 1.f);
        mw = mask * w;
        atomicAdd(&g_deg2[c], mw);
    }
    g_mw[e] = mw;
}

// ---------------- K7: conv2 aggregation (2 lanes/edge, float4 RED into d_out) ----
__global__ void __launch_bounds__(256) k_conv2_agg(float* __restrict__ out, int E) {
    int t = blockIdx.x * blockDim.x + threadIdx.x;
    int e = t >> 1;
    if (e >= E) return;
    float mw = g_mw[e];
    if (mw == 0.f) return;
    int half = t & 1;
    int r = g_row[e], c = g_col[e];
    float norm = g_deg2[r] * mw * g_deg2[c];  // dinv2[r]*mw*dinv2[c]
    float4 v = ((const float4*)g_hw)[r * 2 + half];
    v.x *= norm; v.y *= norm; v.z *= norm; v.w *= norm;
    red_add_v4(&((float4*)out)[c * 2 + half], v);
}

// ---------------- K8: output finalize (self loop + bias) ----------------
__global__ void k_final(float* __restrict__ out, const float* __restrict__ b1, int N) {
    int i = blockIdx.x * blockDim.x + threadIdx.x;
    if (i >= N * H1) return;
    int n = i >> 3, j = i & 7;
    float d = g_deg2[n];
    out[i] += g_hw[i] * d * d + b1[j];
}

// ---------------- launch ----------------
extern "C" void kernel_launch(void* const* d_in, const int* in_sizes, int n_in,
                              void* d_out, int out_size) {
    const float* x     = (const float*)d_in[0];
    const void*  eidx  = d_in[1];
    const float* W0    = (const float*)d_in[2];
    const float* b0    = (const float*)d_in[3];
    const float* W1    = (const float*)d_in[4];
    const float* b1    = (const float*)d_in[5];
    const float* Wnb   = (const float*)d_in[6];
    const float* bnb   = (const float*)d_in[7];
    const float* Wself = (const float*)d_in[8];
    const float* bself = (const float*)d_in[9];
    const float* Watt  = (const float*)d_in[10];
    const float* batt  = (const float*)d_in[11];
    float* out = (float*)d_out;

    int N = in_sizes[0] / IN_DIM;
    int E = in_sizes[1] / 2;

    float* degp  = nullptr; cudaGetSymbolAddress((void**)&degp,  g_deg);
    float* deg2p = nullptr; cudaGetSymbolAddress((void**)&deg2p, g_deg2);

    k_init<<<(N * H0 + 255) / 256, 256>>>(eidx, Wnb, bnb, Wself, bself, Watt, batt, out, N);
    k_convert<<<(E + 255) / 256, 256>>>(eidx, E);
    k_gemm_xw<<<(N + 127) / 128, 128>>>(x, W0, N);
    k_rsqrt<<<(N + 255) / 256, 256>>>(degp, N);
    k_conv1_agg<<<(E * 8 + 255) / 256, 256>>>(E);
    k_node<<<(N * 32 + 255) / 256, 256>>>(b0, W1, N);
    k_edge_gate<<<(E + 255) / 256, 256>>>(E);
    k_rsqrt<<<(N + 255) / 256, 256>>>(deg2p, N);
    k_conv2_agg<<<(E * 2 + 255) / 256, 256>>>(out, E);
    k_final<<<(N * H1 + 255) / 256, 256>>>(out, b1, N);
}

// round 3
// speedup vs baseline: 1.2217x; 1.2217x over previous
#include <cuda_runtime.h>

#define N_NODES 100000
#define N_EDGES 1600000
#define IN_DIM 512
#define H0 32
#define H1 8

// ---------------- scratch (static device globals; no allocation) ----------------
__device__ float g_xw[N_NODES * H0];    // x @ W0
__device__ float g_dinv[N_NODES];       // rsqrt(deg1)
__device__ float g_dinv2[N_NODES];      // rsqrt(deg2)
__device__ int   g_cnt[N_NODES];        // in-degree (edges only)
__device__ int   g_base[N_NODES];       // CSR segment start
__device__ int   g_woff[N_NODES];       // scatter cursor
__device__ int   g_row[N_EDGES];
__device__ int   g_col[N_EDGES];
__device__ int   g_srow[N_EDGES];       // CSR: source node per in-edge, grouped by target
__device__ float g_a1[N_NODES];
__device__ float g_a2[N_NODES];
__device__ float g_hw[N_NODES * H1];    // h @ W1
__device__ float g_wa1[H0];
__device__ float g_wa2[H0];
__device__ float g_c0;
__device__ int   g_is64;
__device__ int   g_bsum[128];           // block sums for scan (98 used)

// ---------------- K0: init + tiny precomputes + dtype detection ----------------
__global__ void k_init(const void* __restrict__ edge_raw,
                       const float* __restrict__ Wnb, const float* __restrict__ bnb,
                       const float* __restrict__ Wself, const float* __restrict__ bself,
                       const float* __restrict__ Watt, const float* __restrict__ batt,
                       int N) {
    int i = blockIdx.x * blockDim.x + threadIdx.x;
    if (i < N) g_cnt[i] = 0;
    if (blockIdx.x == 0) {
        if (threadIdx.x < H0) {
            int k = threadIdx.x;
            float s1 = 0.f, s2 = 0.f;
            #pragma unroll
            for (int j = 0; j < 8; j++) {
                s1 += Wnb[k * 8 + j] * Watt[j];
                s2 += Wself[k * 8 + j] * Watt[8 + j];
            }
            g_wa1[k] = s1; g_wa2[k] = s2;
        }
        if (threadIdx.x == 0) {
            float c = batt[0];
            #pragma unroll
            for (int j = 0; j < 8; j++) c += bnb[j] * Watt[j] + bself[j] * Watt[8 + j];
            g_c0 = c;
            const int* p = (const int*)edge_raw;
            int is64 = 1;
            for (int s = 1; s < 128; s += 2) if (p[s] != 0) { is64 = 0; break; }
            g_is64 = is64;
        }
    }
}

// ---------------- K1: edge index convert + in-degree histogram ----------------
__global__ void k_convert(const void* __restrict__ edge_raw, int E) {
    int e = blockIdx.x * blockDim.x + threadIdx.x;
    if (e >= E) return;
    int r, c;
    if (g_is64) {
        const long long* p = (const long long*)edge_raw;
        r = (int)p[e]; c = (int)p[E + e];
    } else {
        const int* p = (const int*)edge_raw;
        r = p[e]; c = p[E + e];
    }
    g_row[e] = r; g_col[e] = c;
    atomicAdd(&g_cnt[c], 1);
}

// ---------------- scan pass 1: per-block (1024) exclusive scan ----------------
__global__ void __launch_bounds__(1024) k_scan1(int N) {
    __shared__ int s[2048];
    int t = threadIdx.x;
    int i = blockIdx.x * 1024 + t;
    int v = (i < N) ? g_cnt[i] : 0;
    s[t] = v;
    __syncthreads();
    int p = 0;
    #pragma unroll
    for (int off = 1; off < 1024; off <<= 1) {
        int x = s[p + t];
        if (t >= off) x += s[p + t - off];
        p ^= 1024;
        s[p + t] = x;
        __syncthreads();
    }
    int inc = s[p + t];
    if (i < N) g_base[i] = inc - v;  // local exclusive
    if (t == 1023) g_bsum[blockIdx.x] = inc;
}

// ---------------- scan pass 2: scan of block sums (<=128) ----------------
__global__ void __launch_bounds__(128) k_scan2(int nb) {
    __shared__ int s[256];
    int t = threadIdx.x;
    int v = (t < nb) ? g_bsum[t] : 0;
    s[t] = v;
    __syncthreads();
    int p = 0;
    #pragma unroll
    for (int off = 1; off < 128; off <<= 1) {
        int x = s[p + t];
        if (t >= off) x += s[p + t - off];
        p ^= 128;
        s[p + t] = x;
        __syncthreads();
    }
    if (t < nb) g_bsum[t] = s[p + t] - v;  // exclusive
}

// ---------------- scan pass 3: apply offsets + dinv ----------------
__global__ void k_scan3(int N) {
    int i = blockIdx.x * blockDim.x + threadIdx.x;
    if (i >= N) return;
    int b = g_base[i] + g_bsum[i >> 10];
    g_base[i] = b;
    g_woff[i] = b;
    g_dinv[i] = rsqrtf(1.f + (float)g_cnt[i]);
}

// ---------------- K2: scatter edges into CSR (grouped by target) ----------------
__global__ void k_scatter(int E) {
    int e = blockIdx.x * blockDim.x + threadIdx.x;
    if (e >= E) return;
    int c = g_col[e];
    int p = atomicAdd(&g_woff[c], 1);
    g_srow[p] = g_row[e];
}

// ---------------- K3: xw = x @ W0 (fp32 tiled) ----------------
__global__ void __launch_bounds__(128) k_gemm_xw(const float* __restrict__ x,
                                                 const float* __restrict__ W0, int N) {
    __shared__ float sX[32][128];
    __shared__ float sW[32][32];
    int t = threadIdx.x;
    int row0 = blockIdx.x * 128;
    int rid = t >> 3;
    int cid = t & 7;
    float acc[8][4];
    #pragma unroll
    for (int i = 0; i < 8; i++)
        #pragma unroll
        for (int j = 0; j < 4; j++) acc[i][j] = 0.f;

    for (int kc = 0; kc < IN_DIM; kc += 32) {
        const float4* w4 = (const float4*)(W0 + kc * H0);
        float4* s4 = (float4*)&sW[0][0];
        s4[t] = w4[t];
        s4[t + 128] = w4[t + 128];
        int lr = t >> 3;
        int kg = (t & 7) * 4;
        #pragma unroll
        for (int it = 0; it < 8; it++) {
            int r = lr + it * 16;
            int grow = row0 + r;
            float4 v = make_float4(0.f, 0.f, 0.f, 0.f);
            if (grow < N) v = *(const float4*)&x[(size_t)grow * IN_DIM + kc + kg];
            sX[kg + 0][r] = v.x; sX[kg + 1][r] = v.y;
            sX[kg + 2][r] = v.z; sX[kg + 3][r] = v.w;
        }
        __syncthreads();
        #pragma unroll 8
        for (int kk = 0; kk < 32; kk++) {
            float4 wv = *(float4*)&sW[kk][cid * 4];
            float4 xa = *(float4*)&sX[kk][rid * 8];
            float4 xb = *(float4*)&sX[kk][rid * 8 + 4];
            float ax[8] = {xa.x, xa.y, xa.z, xa.w, xb.x, xb.y, xb.z, xb.w};
            float wc[4] = {wv.x, wv.y, wv.z, wv.w};
            #pragma unroll
            for (int i = 0; i < 8; i++)
                #pragma unroll
                for (int j = 0; j < 4; j++)
                    acc[i][j] = fmaf(ax[i], wc[j], acc[i][j]);
        }
        __syncthreads();
    }
    #pragma unroll
    for (int i = 0; i < 8; i++) {
        int grow = row0 + rid * 8 + i;
        if (grow < N) {
            float4 v = make_float4(acc[i][0], acc[i][1], acc[i][2], acc[i][3]);
            *(float4*)&g_xw[grow * H0 + cid * 4] = v;
        }
    }
}

// ---------------- K4: conv1 gather + node finalize + attention + h@W1 --------
// 8 lanes per node: lane j owns float4 chunk j of the 32-wide h.
__global__ void __launch_bounds__(256) k_conv1node(const float* __restrict__ b0,
                                                   const float* __restrict__ W1, int N) {
    __shared__ float sh[8][128];
    __shared__ float sW1[H0 * H1];
    if (threadIdx.x < H0 * H1) sW1[threadIdx.x] = W1[threadIdx.x];
    __syncthreads();

    int t = blockIdx.x * blockDim.x + threadIdx.x;
    int n = t >> 3;
    if (n >= N) return;
    int lane = threadIdx.x & 31;
    int wid = threadIdx.x >> 5;
    int niw = lane >> 3;
    int j = lane & 7;

    float dc = g_dinv[n];
    int s0 = g_base[n], cnt = g_cnt[n];
    const float4* xw4 = (const float4*)g_xw;
    float4 acc = make_float4(0.f, 0.f, 0.f, 0.f);
    for (int i = 0; i < cnt; i++) {
        int r = g_srow[s0 + i];
        float nr = g_dinv[r] * dc;
        float4 v = xw4[r * 8 + j];
        acc.x = fmaf(nr, v.x, acc.x);
        acc.y = fmaf(nr, v.y, acc.y);
        acc.z = fmaf(nr, v.z, acc.z);
        acc.w = fmaf(nr, v.w, acc.w);
    }
    float4 vs = xw4[n * 8 + j];
    float ds = dc * dc;
    float4 bb = ((const float4*)b0)[j];
    float4 h;
    h.x = acc.x + ds * vs.x + bb.x;
    h.y = acc.y + ds * vs.y + bb.y;
    h.z = acc.z + ds * vs.z + bb.z;
    h.w = acc.w + ds * vs.w + bb.w;

    // attention scalars
    float4 w1 = ((const float4*)g_wa1)[j];
    float4 w2 = ((const float4*)g_wa2)[j];
    float v1 = h.x * w1.x + h.y * w1.y + h.z * w1.z + h.w * w1.w;
    float v2 = h.x * w2.x + h.y * w2.y + h.z * w2.z + h.w * w2.w;
    #pragma unroll
    for (int o = 1; o < 8; o <<= 1) {
        v1 += __shfl_xor_sync(0xffffffffu, v1, o);
        v2 += __shfl_xor_sync(0xffffffffu, v2, o);
    }
    if (j == 0) { g_a1[n] = v1; g_a2[n] = v2; }

    // hw = h @ W1 : share h via smem within the 8-lane group
    float* shn = &sh[wid][niw * 32];
    ((float4*)shn)[j] = h;
    __syncwarp();
    float o = 0.f;
    #pragma unroll
    for (int k = 0; k < 32; k++) o = fmaf(shn[k], sW1[k * 8 + j], o);
    g_hw[n * 8 + j] = o;
}

// ---------------- K5: deg2 gather (gated degree), 4 lanes/node ----------------
__global__ void __launch_bounds__(256) k_deg2(int N) {
    int t = blockIdx.x * blockDim.x + threadIdx.x;
    int n = t >> 2;
    if (n >= N) return;
    int l = t & 3;
    float a2c = g_a2[n] + g_c0;
    int s0 = g_base[n], cnt = g_cnt[n];
    float sum = 0.f;
    for (int i = l; i < cnt; i += 4) {
        int r = g_srow[s0 + i];
        float w = g_a1[r] + a2c;
        if (w > 0.f) {
            float mask = fminf(1.01f / (1.f + __expf(-w)), 1.f);
            sum += mask * w;
        }
    }
    sum += __shfl_xor_sync(0xffffffffu, sum, 1);
    sum += __shfl_xor_sync(0xffffffffu, sum, 2);
    if (l == 0) g_dinv2[n] = rsqrtf(1.f + sum);
}

// ---------------- K6: conv2 gather -> out (2 lanes/node) ----------------
__global__ void __launch_bounds__(256) k_conv2(float* __restrict__ out,
                                               const float* __restrict__ b1, int N) {
    int t = blockIdx.x * blockDim.x + threadIdx.x;
    int n = t >> 1;
    if (n >= N) return;
    int j = t & 1;
    float a2c = g_a2[n] + g_c0;
    float d2n = g_dinv2[n];
    int s0 = g_base[n], cnt = g_cnt[n];
    const float4* hw4 = (const float4*)g_hw;
    float4 acc = make_float4(0.f, 0.f, 0.f, 0.f);
    for (int i = 0; i < cnt; i++) {
        int r = g_srow[s0 + i];
        float w = g_a1[r] + a2c;
        if (w <= 0.f) continue;
        float mask = fminf(1.01f / (1.f + __expf(-w)), 1.f);
        float nr = mask * w * g_dinv2[r];
        float4 v = hw4[r * 2 + j];
        acc.x = fmaf(nr, v.x, acc.x);
        acc.y = fmaf(nr, v.y, acc.y);
        acc.z = fmaf(nr, v.z, acc.z);
        acc.w = fmaf(nr, v.w, acc.w);
    }
    float4 self = hw4[n * 2 + j];
    float4 bb = ((const float4*)b1)[j];
    float4 o;
    o.x = d2n * (acc.x + d2n * self.x) + bb.x;
    o.y = d2n * (acc.y + d2n * self.y) + bb.y;
    o.z = d2n * (acc.z + d2n * self.z) + bb.z;
    o.w = d2n * (acc.w + d2n * self.w) + bb.w;
    ((float4*)out)[n * 2 + j] = o;
}

// ---------------- launch ----------------
extern "C" void kernel_launch(void* const* d_in, const int* in_sizes, int n_in,
                              void* d_out, int out_size) {
    const float* x     = (const float*)d_in[0];
    const void*  eidx  = d_in[1];
    const float* W0    = (const float*)d_in[2];
    const float* b0    = (const float*)d_in[3];
    const float* W1    = (const float*)d_in[4];
    const float* b1    = (const float*)d_in[5];
    const float* Wnb   = (const float*)d_in[6];
    const float* bnb   = (const float*)d_in[7];
    const float* Wself = (const float*)d_in[8];
    const float* bself = (const float*)d_in[9];
    const float* Watt  = (const float*)d_in[10];
    const float* batt  = (const float*)d_in[11];
    float* out = (float*)d_out;

    int N = in_sizes[0] / IN_DIM;
    int E = in_sizes[1] / 2;
    int NB = (N + 1023) / 1024;

    k_init<<<(N + 255) / 256, 256>>>(eidx, Wnb, bnb, Wself, bself, Watt, batt, N);
    k_convert<<<(E + 255) / 256, 256>>>(eidx, E);
    k_gemm_xw<<<(N + 127) / 128, 128>>>(x, W0, N);
    k_scan1<<<NB, 1024>>>(N);
    k_scan2<<<1, 128>>>(NB);
    k_scan3<<<(N + 255) / 256, 256>>>(N);
    k_scatter<<<(E + 255) / 256, 256>>>(E);
    k_conv1node<<<(N * 8 + 255) / 256, 256>>>(b0, W1, N);
    k_deg2<<<(N * 4 + 255) / 256, 256>>>(N);
    k_conv2<<<(N * 2 + 255) / 256, 256>>>(out, b1, N);
}

// round 5
// speedup vs baseline: 1.3940x; 1.1411x over previous
#include <cuda_runtime.h>
#include <cstdint>

#define N_NODES 100000
#define N_EDGES 1600000
#define IN_DIM 512
#define H0 32
#define H1 8

// ---------------- scratch (static device globals; no allocation) ----------------
__device__ float g_xw[N_NODES * H0];    // x @ W0
__device__ float g_dinv[N_NODES];       // rsqrt(deg1)
__device__ float g_dinv2[N_NODES];      // rsqrt(deg2)
__device__ int   g_cnt[N_NODES];        // in-degree (edges only)
__device__ int   g_base[N_NODES];       // CSR segment start
__device__ int   g_woff[N_NODES];       // scatter cursor
__device__ int   g_row[N_EDGES];
__device__ int   g_col[N_EDGES];
__device__ int   g_srow[N_EDGES];       // CSR: source node per in-edge, grouped by target
__device__ float g_a1[N_NODES];
__device__ float g_a2[N_NODES];
__device__ float g_hw[N_NODES * H1];    // h @ W1
__device__ float g_wa1[H0];
__device__ float g_wa2[H0];
__device__ float g_c0;
__device__ int   g_is64;
__device__ int   g_bsum[128];           // block sums for scan (98 used)
__device__ float4 g_bfrag[64 * 4 * 32]; // W0 tf32 frags: [chunk][ntile][lane] = {hi0,hi1,lo0,lo1}

// ---------------- tf32 helpers ----------------
__device__ __forceinline__ uint32_t f2tf32(float f) {
    uint32_t r;
    asm("cvt.rna.tf32.f32 %0, %1;" : "=r"(r) : "f"(f));
    return r;
}

__device__ __forceinline__ void mma_tf32(float4& c, uint32_t a0, uint32_t a1,
                                         uint32_t a2, uint32_t a3,
                                         uint32_t b0, uint32_t b1) {
    asm volatile(
        "mma.sync.aligned.m16n8k8.row.col.f32.tf32.tf32.f32 "
        "{%0,%1,%2,%3}, {%4,%5,%6,%7}, {%8,%9}, {%0,%1,%2,%3};"
        : "+f"(c.x), "+f"(c.y), "+f"(c.z), "+f"(c.w)
        : "r"(a0), "r"(a1), "r"(a2), "r"(a3), "r"(b0), "r"(b1));
}

// ---------------- K0: init + tiny precomputes + dtype detection ----------------
__global__ void k_init(const void* __restrict__ edge_raw,
                       const float* __restrict__ Wnb, const float* __restrict__ bnb,
                       const float* __restrict__ Wself, const float* __restrict__ bself,
                       const float* __restrict__ Watt, const float* __restrict__ batt,
                       int N) {
    int i = blockIdx.x * blockDim.x + threadIdx.x;
    if (i < N) g_cnt[i] = 0;
    if (blockIdx.x == 0) {
        if (threadIdx.x < H0) {
            int k = threadIdx.x;
            float s1 = 0.f, s2 = 0.f;
            #pragma unroll
            for (int j = 0; j < 8; j++) {
                s1 += Wnb[k * 8 + j] * Watt[j];
                s2 += Wself[k * 8 + j] * Watt[8 + j];
            }
            g_wa1[k] = s1; g_wa2[k] = s2;
        }
        if (threadIdx.x == 0) {
            float c = batt[0];
            #pragma unroll
            for (int j = 0; j < 8; j++) c += bnb[j] * Watt[j] + bself[j] * Watt[8 + j];
            g_c0 = c;
            const int* p = (const int*)edge_raw;
            int is64 = 1;
            for (int s = 1; s < 128; s += 2) if (p[s] != 0) { is64 = 0; break; }
            g_is64 = is64;
        }
    }
}

// ---------------- K0b: bake W0 into tf32 hi/lo fragment layout ----------------
// frag index: [chunk(64)][ntile(4)][lane(32)]; lane: gid=lane>>2 (n), tig=lane&3 (k)
__global__ void k_bfrag(const float* __restrict__ W0) {
    int i = blockIdx.x * blockDim.x + threadIdx.x;
    if (i >= 64 * 4 * 32) return;
    int lane = i & 31;
    int nt = (i >> 5) & 3;
    int chunk = i >> 7;
    int gid = lane >> 2, tig = lane & 3;
    int n = nt * 8 + gid;
    int k = chunk * 8 + tig;
    float b0f = W0[k * H0 + n];
    float b1f = W0[(k + 4) * H0 + n];
    uint32_t h0 = f2tf32(b0f);
    uint32_t h1 = f2tf32(b1f);
    uint32_t l0 = f2tf32(b0f - __uint_as_float(h0));
    uint32_t l1 = f2tf32(b1f - __uint_as_float(h1));
    g_bfrag[i] = make_float4(__uint_as_float(h0), __uint_as_float(h1),
                             __uint_as_float(l0), __uint_as_float(l1));
}

// ---------------- K1: edge index convert + in-degree histogram ----------------
__global__ void k_convert(const void* __restrict__ edge_raw, int E) {
    int e = blockIdx.x * blockDim.x + threadIdx.x;
    if (e >= E) return;
    int r, c;
    if (g_is64) {
        const long long* p = (const long long*)edge_raw;
        r = (int)p[e]; c = (int)p[E + e];
    } else {
        const int* p = (const int*)edge_raw;
        r = p[e]; c = p[E + e];
    }
    g_row[e] = r; g_col[e] = c;
    atomicAdd(&g_cnt[c], 1);
}

// ---------------- scan pass 1 ----------------
__global__ void __launch_bounds__(1024) k_scan1(int N) {
    __shared__ int s[2048];
    int t = threadIdx.x;
    int i = blockIdx.x * 1024 + t;
    int v = (i < N) ? g_cnt[i] : 0;
    s[t] = v;
    __syncthreads();
    int p = 0;
    #pragma unroll
    for (int off = 1; off < 1024; off <<= 1) {
        int x = s[p + t];
        if (t >= off) x += s[p + t - off];
        p ^= 1024;
        s[p + t] = x;
        __syncthreads();
    }
    int inc = s[p + t];
    if (i < N) g_base[i] = inc - v;
    if (t == 1023) g_bsum[blockIdx.x] = inc;
}

// ---------------- scan pass 2 ----------------
__global__ void __launch_bounds__(128) k_scan2(int nb) {
    __shared__ int s[256];
    int t = threadIdx.x;
    int v = (t < nb) ? g_bsum[t] : 0;
    s[t] = v;
    __syncthreads();
    int p = 0;
    #pragma unroll
    for (int off = 1; off < 128; off <<= 1) {
        int x = s[p + t];
        if (t >= off) x += s[p + t - off];
        p ^= 128;
        s[p + t] = x;
        __syncthreads();
    }
    if (t < nb) g_bsum[t] = s[p + t] - v;
}

// ---------------- scan pass 3 ----------------
__global__ void k_scan3(int N) {
    int i = blockIdx.x * blockDim.x + threadIdx.x;
    if (i >= N) return;
    int b = g_base[i] + g_bsum[i >> 10];
    g_base[i] = b;
    g_woff[i] = b;
    g_dinv[i] = rsqrtf(1.f + (float)g_cnt[i]);
}

// ---------------- K2: scatter edges into CSR ----------------
__global__ void k_scatter(int E) {
    int e = blockIdx.x * blockDim.x + threadIdx.x;
    if (e >= E) return;
    int c = g_col[e];
    int p = atomicAdd(&g_woff[c], 1);
    g_srow[p] = g_row[e];
}

// ---------------- K3: xw = x @ W0 via tf32 tensor cores (3xTF32 split) -------
// block: 256 threads / 8 warps; warp = 16 rows x 32 cols; block tile M=128.
__global__ void __launch_bounds__(256) k_gemm_tc(const float* __restrict__ x, int N) {
    __shared__ float sA[128 * 36];  // 128 rows x 32 k, stride 36 (pad) = 18KB
    int tid = threadIdx.x;
    int warp = tid >> 5;
    int lane = tid & 31;
    int gid = lane >> 2;   // 0..7
    int tig = lane & 3;    // 0..3
    int row0 = blockIdx.x * 128;
    int wr0 = warp * 16;

    float4 C[4];
    #pragma unroll
    for (int nt = 0; nt < 4; nt++) C[nt] = make_float4(0.f, 0.f, 0.f, 0.f);

    for (int stage = 0; stage < 16; stage++) {
        int kc = stage * 32;
        // stage A: 128 rows x 32 cols, 1024 float4, 4 per thread
        #pragma unroll
        for (int i = 0; i < 4; i++) {
            int idx = tid + i * 256;
            int r = idx >> 3;
            int cg = idx & 7;
            int grow = row0 + r;
            float4 v = make_float4(0.f, 0.f, 0.f, 0.f);
            if (grow < N) v = *(const float4*)&x[(size_t)grow * IN_DIM + kc + cg * 4];
            *(float4*)&sA[r * 36 + cg * 4] = v;
        }
        __syncthreads();

        #pragma unroll
        for (int ch = 0; ch < 4; ch++) {
            int k0 = ch * 8;
            int gchunk = stage * 4 + ch;
            int rb = (wr0 + gid) * 36;
            float f0 = sA[rb + k0 + tig];
            float f1 = sA[rb + 8 * 36 + k0 + tig];
            float f2 = sA[rb + k0 + tig + 4];
            float f3 = sA[rb + 8 * 36 + k0 + tig + 4];
            uint32_t ah0 = f2tf32(f0), ah1 = f2tf32(f1), ah2 = f2tf32(f2), ah3 = f2tf32(f3);
            uint32_t al0 = f2tf32(f0 - __uint_as_float(ah0));
            uint32_t al1 = f2tf32(f1 - __uint_as_float(ah1));
            uint32_t al2 = f2tf32(f2 - __uint_as_float(ah2));
            uint32_t al3 = f2tf32(f3 - __uint_as_float(ah3));
            #pragma unroll
            for (int nt = 0; nt < 4; nt++) {
                float4 bf = g_bfrag[(gchunk * 4 + nt) * 32 + lane];
                uint32_t bh0 = __float_as_uint(bf.x), bh1 = __float_as_uint(bf.y);
                uint32_t bl0 = __float_as_uint(bf.z), bl1 = __float_as_uint(bf.w);
                mma_tf32(C[nt], ah0, ah1, ah2, ah3, bl0, bl1);  // hi*lo
                mma_tf32(C[nt], al0, al1, al2, al3, bh0, bh1);  // lo*hi
                mma_tf32(C[nt], ah0, ah1, ah2, ah3, bh0, bh1);  // hi*hi
            }
        }
        __syncthreads();
    }

    // store C: c.x,c.y at (gid, n0+2tig, +1); c.z,c.w at (gid+8, ...)
    int r0 = row0 + wr0 + gid;
    int r1 = r0 + 8;
    #pragma unroll
    for (int nt = 0; nt < 4; nt++) {
        int cidx = nt * 4 + tig;  // float2 index within the 32-col row
        if (r0 < N) ((float2*)g_xw)[r0 * 16 + cidx] = make_float2(C[nt].x, C[nt].y);
        if (r1 < N) ((float2*)g_xw)[r1 * 16 + cidx] = make_float2(C[nt].z, C[nt].w);
    }
}

// ---------------- K4: conv1 gather + node finalize + attention + h@W1 --------
__global__ void __launch_bounds__(256) k_conv1node(const float* __restrict__ b0,
                                                   const float* __restrict__ W1, int N) {
    __shared__ float sh[8][128];
    __shared__ float sW1[H0 * H1];
    if (threadIdx.x < H0 * H1) sW1[threadIdx.x] = W1[threadIdx.x];
    __syncthreads();

    int t = blockIdx.x * blockDim.x + threadIdx.x;
    int n = t >> 3;
    if (n >= N) return;
    int lane = threadIdx.x & 31;
    int wid = threadIdx.x >> 5;
    int niw = lane >> 3;
    int j = lane & 7;

    float dc = g_dinv[n];
    int s0 = g_base[n], cnt = g_cnt[n];
    const float4* xw4 = (const float4*)g_xw;
    float4 acc = make_float4(0.f, 0.f, 0.f, 0.f);
    for (int i = 0; i < cnt; i++) {
        int r = g_srow[s0 + i];
        float nr = g_dinv[r] * dc;
        float4 v = xw4[r * 8 + j];
        acc.x = fmaf(nr, v.x, acc.x);
        acc.y = fmaf(nr, v.y, acc.y);
        acc.z = fmaf(nr, v.z, acc.z);
        acc.w = fmaf(nr, v.w, acc.w);
    }
    float4 vs = xw4[n * 8 + j];
    float ds = dc * dc;
    float4 bb = ((const float4*)b0)[j];
    float4 h;
    h.x = acc.x + ds * vs.x + bb.x;
    h.y = acc.y + ds * vs.y + bb.y;
    h.z = acc.z + ds * vs.z + bb.z;
    h.w = acc.w + ds * vs.w + bb.w;

    float4 w1 = ((const float4*)g_wa1)[j];
    float4 w2 = ((const float4*)g_wa2)[j];
    float v1 = h.x * w1.x + h.y * w1.y + h.z * w1.z + h.w * w1.w;
    float v2 = h.x * w2.x + h.y * w2.y + h.z * w2.z + h.w * w2.w;
    #pragma unroll
    for (int o = 1; o < 8; o <<= 1) {
        v1 += __shfl_xor_sync(0xffffffffu, v1, o);
        v2 += __shfl_xor_sync(0xffffffffu, v2, o);
    }
    if (j == 0) { g_a1[n] = v1; g_a2[n] = v2; }

    float* shn = &sh[wid][niw * 32];
    ((float4*)shn)[j] = h;
    __syncwarp();
    float o = 0.f;
    #pragma unroll
    for (int k = 0; k < 32; k++) o = fmaf(shn[k], sW1[k * 8 + j], o);
    g_hw[n * 8 + j] = o;
}

// ---------------- K5: deg2 gather ----------------
__global__ void __launch_bounds__(256) k_deg2(int N) {
    int t = blockIdx.x * blockDim.x + threadIdx.x;
    int n = t >> 2;
    if (n >= N) return;
    int l = t & 3;
    float a2c = g_a2[n] + g_c0;
    int s0 = g_base[n], cnt = g_cnt[n];
    float sum = 0.f;
    for (int i = l; i < cnt; i += 4) {
        int r = g_srow[s0 + i];
        float w = g_a1[r] + a2c;
        if (w > 0.f) {
            float mask = fminf(1.01f / (1.f + __expf(-w)), 1.f);
            sum += mask * w;
        }
    }
    sum += __shfl_xor_sync(0xffffffffu, sum, 1);
    sum += __shfl_xor_sync(0xffffffffu, sum, 2);
    if (l == 0) g_dinv2[n] = rsqrtf(1.f + sum);
}

// ---------------- K6: conv2 gather -> out ----------------
__global__ void __launch_bounds__(256) k_conv2(float* __restrict__ out,
                                               const float* __restrict__ b1, int N) {
    int t = blockIdx.x * blockDim.x + threadIdx.x;
    int n = t >> 1;
    if (n >= N) return;
    int j = t & 1;
    float a2c = g_a2[n] + g_c0;
    float d2n = g_dinv2[n];
    int s0 = g_base[n], cnt = g_cnt[n];
    const float4* hw4 = (const float4*)g_hw;
    float4 acc = make_float4(0.f, 0.f, 0.f, 0.f);
    for (int i = 0; i < cnt; i++) {
        int r = g_srow[s0 + i];
        float w = g_a1[r] + a2c;
        if (w <= 0.f) continue;
        float mask = fminf(1.01f / (1.f + __expf(-w)), 1.f);
        float nr = mask * w * g_dinv2[r];
        float4 v = hw4[r * 2 + j];
        acc.x = fmaf(nr, v.x, acc.x);
        acc.y = fmaf(nr, v.y, acc.y);
        acc.z = fmaf(nr, v.z, acc.z);
        acc.w = fmaf(nr, v.w, acc.w);
    }
    float4 self = hw4[n * 2 + j];
    float4 bb = ((const float4*)b1)[j];
    float4 o;
    o.x = d2n * (acc.x + d2n * self.x) + bb.x;
    o.y = d2n * (acc.y + d2n * self.y) + bb.y;
    o.z = d2n * (acc.z + d2n * self.z) + bb.z;
    o.w = d2n * (acc.w + d2n * self.w) + bb.w;
    ((float4*)out)[n * 2 + j] = o;
}

// ---------------- launch ----------------
extern "C" void kernel_launch(void* const* d_in, const int* in_sizes, int n_in,
                              void* d_out, int out_size) {
    const float* x     = (const float*)d_in[0];
    const void*  eidx  = d_in[1];
    const float* W0    = (const float*)d_in[2];
    const float* b0    = (const float*)d_in[3];
    const float* W1    = (const float*)d_in[4];
    const float* b1    = (const float*)d_in[5];
    const float* Wnb   = (const float*)d_in[6];
    const float* bnb   = (const float*)d_in[7];
    const float* Wself = (const float*)d_in[8];
    const float* bself = (const float*)d_in[9];
    const float* Watt  = (const float*)d_in[10];
    const float* batt  = (const float*)d_in[11];
    float* out = (float*)d_out;

    int N = in_sizes[0] / IN_DIM;
    int E = in_sizes[1] / 2;
    int NB = (N + 1023) / 1024;

    k_init<<<(N + 255) / 256, 256>>>(eidx, Wnb, bnb, Wself, bself, Watt, batt, N);
    k_bfrag<<<32, 256>>>(W0);
    k_convert<<<(E + 255) / 256, 256>>>(eidx, E);
    k_gemm_tc<<<(N + 127) / 128, 256>>>(x, N);
    k_scan1<<<NB, 1024>>>(N);
    k_scan2<<<1, 128>>>(NB);
    k_scan3<<<(N + 255) / 256, 256>>>(N);
    k_scatter<<<(E + 255) / 256, 256>>>(E);
    k_conv1node<<<(N * 8 + 255) / 256, 256>>>(b0, W1, N);
    k_deg2<<<(N * 4 + 255) / 256, 256>>>(N);
    k_conv2<<<(N * 2 + 255) / 256, 256>>>(out, b1, N);
}

// round 6
// speedup vs baseline: 1.4259x; 1.0229x over previous
#include <cuda_runtime.h>
#include <cstdint>

#define N_NODES 100000
#define N_EDGES 1600000
#define IN_DIM 512
#define H0 32
#define H1 8

// ---------------- scratch (static device globals; no allocation) ----------------
__device__ float g_xw[N_NODES * H0];    // x @ W0
__device__ float g_dinv[N_NODES];       // rsqrt(deg1)
__device__ float g_dinv2[N_NODES];      // rsqrt(deg2)
__device__ int   g_cnt[N_NODES];        // in-degree (edges only)
__device__ int   g_base[N_NODES];       // CSR segment start
__device__ int   g_woff[N_NODES];       // scatter cursor
__device__ int   g_row[N_EDGES];
__device__ int   g_col[N_EDGES];
__device__ int   g_srow[N_EDGES];       // CSR: source node per in-edge, grouped by target
__device__ float g_a1[N_NODES];
__device__ float g_a2[N_NODES];
__device__ float g_hw[N_NODES * H1];    // h @ W1
__device__ float g_wa1[H0];
__device__ float g_wa2[H0];
__device__ float g_c0;
__device__ int   g_is64;
__device__ int   g_bsum[128];           // block sums for scan (98 used)
__device__ float4 g_bfrag[64 * 4 * 32]; // W0 tf32 frags: [chunk][ntile][lane] = {hi0,hi1,lo0,lo1}

// ---------------- tf32 helpers ----------------
__device__ __forceinline__ uint32_t f2tf32(float f) {
    uint32_t r;
    asm("cvt.rna.tf32.f32 %0, %1;" : "=r"(r) : "f"(f));
    return r;
}

__device__ __forceinline__ void mma_tf32(float4& c, uint32_t a0, uint32_t a1,
                                         uint32_t a2, uint32_t a3,
                                         uint32_t b0, uint32_t b1) {
    asm volatile(
        "mma.sync.aligned.m16n8k8.row.col.f32.tf32.tf32.f32 "
        "{%0,%1,%2,%3}, {%4,%5,%6,%7}, {%8,%9}, {%0,%1,%2,%3};"
        : "+f"(c.x), "+f"(c.y), "+f"(c.z), "+f"(c.w)
        : "r"(a0), "r"(a1), "r"(a2), "r"(a3), "r"(b0), "r"(b1));
}

// ---------------- K0: init + tiny precomputes + dtype detection ----------------
__global__ void k_init(const void* __restrict__ edge_raw,
                       const float* __restrict__ Wnb, const float* __restrict__ bnb,
                       const float* __restrict__ Wself, const float* __restrict__ bself,
                       const float* __restrict__ Watt, const float* __restrict__ batt,
                       int N) {
    int i = blockIdx.x * blockDim.x + threadIdx.x;
    if (i < N) g_cnt[i] = 0;
    if (blockIdx.x == 0) {
        if (threadIdx.x < H0) {
            int k = threadIdx.x;
            float s1 = 0.f, s2 = 0.f;
            #pragma unroll
            for (int j = 0; j < 8; j++) {
                s1 += Wnb[k * 8 + j] * Watt[j];
                s2 += Wself[k * 8 + j] * Watt[8 + j];
            }
            g_wa1[k] = s1; g_wa2[k] = s2;
        }
        if (threadIdx.x == 0) {
            float c = batt[0];
            #pragma unroll
            for (int j = 0; j < 8; j++) c += bnb[j] * Watt[j] + bself[j] * Watt[8 + j];
            g_c0 = c;
            const int* p = (const int*)edge_raw;
            int is64 = 1;
            for (int s = 1; s < 128; s += 2) if (p[s] != 0) { is64 = 0; break; }
            g_is64 = is64;
        }
    }
}

// ---------------- K0b: bake W0 into tf32 hi/lo fragment layout ----------------
__global__ void k_bfrag(const float* __restrict__ W0) {
    int i = blockIdx.x * blockDim.x + threadIdx.x;
    if (i >= 64 * 4 * 32) return;
    int lane = i & 31;
    int nt = (i >> 5) & 3;
    int chunk = i >> 7;
    int gid = lane >> 2, tig = lane & 3;
    int n = nt * 8 + gid;
    int k = chunk * 8 + tig;
    float b0f = W0[k * H0 + n];
    float b1f = W0[(k + 4) * H0 + n];
    uint32_t h0 = f2tf32(b0f);
    uint32_t h1 = f2tf32(b1f);
    uint32_t l0 = f2tf32(b0f - __uint_as_float(h0));
    uint32_t l1 = f2tf32(b1f - __uint_as_float(h1));
    g_bfrag[i] = make_float4(__uint_as_float(h0), __uint_as_float(h1),
                             __uint_as_float(l0), __uint_as_float(l1));
}

// ---------------- K1: edge index convert + in-degree histogram ----------------
__global__ void k_convert(const void* __restrict__ edge_raw, int E) {
    int e = blockIdx.x * blockDim.x + threadIdx.x;
    if (e >= E) return;
    int r, c;
    if (g_is64) {
        const long long* p = (const long long*)edge_raw;
        r = (int)p[e]; c = (int)p[E + e];
    } else {
        const int* p = (const int*)edge_raw;
        r = p[e]; c = p[E + e];
    }
    g_row[e] = r; g_col[e] = c;
    atomicAdd(&g_cnt[c], 1);
}

// ---------------- scan pass 1 ----------------
__global__ void __launch_bounds__(1024) k_scan1(int N) {
    __shared__ int s[2048];
    int t = threadIdx.x;
    int i = blockIdx.x * 1024 + t;
    int v = (i < N) ? g_cnt[i] : 0;
    s[t] = v;
    __syncthreads();
    int p = 0;
    #pragma unroll
    for (int off = 1; off < 1024; off <<= 1) {
        int x = s[p + t];
        if (t >= off) x += s[p + t - off];
        p ^= 1024;
        s[p + t] = x;
        __syncthreads();
    }
    int inc = s[p + t];
    if (i < N) g_base[i] = inc - v;
    if (t == 1023) g_bsum[blockIdx.x] = inc;
}

// ---------------- scan pass 2 ----------------
__global__ void __launch_bounds__(128) k_scan2(int nb) {
    __shared__ int s[256];
    int t = threadIdx.x;
    int v = (t < nb) ? g_bsum[t] : 0;
    s[t] = v;
    __syncthreads();
    int p = 0;
    #pragma unroll
    for (int off = 1; off < 128; off <<= 1) {
        int x = s[p + t];
        if (t >= off) x += s[p + t - off];
        p ^= 128;
        s[p + t] = x;
        __syncthreads();
    }
    if (t < nb) g_bsum[t] = s[p + t] - v;
}

// ---------------- scan pass 3 ----------------
__global__ void k_scan3(int N) {
    int i = blockIdx.x * blockDim.x + threadIdx.x;
    if (i >= N) return;
    int b = g_base[i] + g_bsum[i >> 10];
    g_base[i] = b;
    g_woff[i] = b;
    g_dinv[i] = rsqrtf(1.f + (float)g_cnt[i]);
}

// ---------------- K2: scatter edges into CSR ----------------
__global__ void k_scatter(int E) {
    int e = blockIdx.x * blockDim.x + threadIdx.x;
    if (e >= E) return;
    int c = g_col[e];
    int p = atomicAdd(&g_woff[c], 1);
    g_srow[p] = g_row[e];
}

// ---------------- K3: xw = x @ W0 via tf32 TC, cp.async double-buffered ------
// block: 256 threads / 8 warps; warp = 16 rows x 32 cols; block tile M=128.
__global__ void __launch_bounds__(256) k_gemm_tc(const float* __restrict__ x, int N) {
    __shared__ float sA[2][128 * 36];  // 2 x 18KB, stride 36 floats (144B, 16B-aligned)
    int tid = threadIdx.x;
    int warp = tid >> 5;
    int lane = tid & 31;
    int gid = lane >> 2;   // 0..7
    int tig = lane & 3;    // 0..3
    int row0 = blockIdx.x * 128;
    int wr0 = warp * 16;
    bool full = (row0 + 128 <= N);

    float4 C[4];
    #pragma unroll
    for (int nt = 0; nt < 4; nt++) C[nt] = make_float4(0.f, 0.f, 0.f, 0.f);

    // stage loader: 1024 float4 (128 rows x 8 groups), 4 cp.async per thread
    auto issue_stage = [&](int buf, int kc) {
        #pragma unroll
        for (int i = 0; i < 4; i++) {
            int idx = tid + i * 256;
            int r = idx >> 3;
            int cg = idx & 7;
            int grow = row0 + r;
            float* dgen = &sA[buf][r * 36 + cg * 4];
            uint32_t dst = (uint32_t)__cvta_generic_to_shared(dgen);
            const float* src = &x[(size_t)grow * IN_DIM + kc + cg * 4];
            if (full || grow < N) {
                asm volatile("cp.async.cg.shared.global [%0], [%1], 16;"
                             :: "r"(dst), "l"(src));
            } else {
                *(float4*)dgen = make_float4(0.f, 0.f, 0.f, 0.f);
            }
        }
        asm volatile("cp.async.commit_group;");
    };

    issue_stage(0, 0);

    for (int s = 0; s < 16; s++) {
        if (s > 0) __syncthreads();  // compute(s-1) done -> safe to refill its buffer
        if (s + 1 < 16) {
            issue_stage((s + 1) & 1, (s + 1) * 32);
            asm volatile("cp.async.wait_group 1;");  // stage s complete, s+1 in flight
        } else {
            asm volatile("cp.async.wait_group 0;");
        }
        __syncthreads();

        const float* A = sA[s & 1];
        #pragma unroll
        for (int ch = 0; ch < 4; ch++) {
            int k0 = ch * 8;
            int gchunk = s * 4 + ch;
            int rb = (wr0 + gid) * 36;
            float f0 = A[rb + k0 + tig];
            float f1 = A[rb + 8 * 36 + k0 + tig];
            float f2 = A[rb + k0 + tig + 4];
            float f3 = A[rb + 8 * 36 + k0 + tig + 4];
            uint32_t ah0 = f2tf32(f0), ah1 = f2tf32(f1), ah2 = f2tf32(f2), ah3 = f2tf32(f3);
            uint32_t al0 = f2tf32(f0 - __uint_as_float(ah0));
            uint32_t al1 = f2tf32(f1 - __uint_as_float(ah1));
            uint32_t al2 = f2tf32(f2 - __uint_as_float(ah2));
            uint32_t al3 = f2tf32(f3 - __uint_as_float(ah3));
            #pragma unroll
            for (int nt = 0; nt < 4; nt++) {
                float4 bf = g_bfrag[(gchunk * 4 + nt) * 32 + lane];
                uint32_t bh0 = __float_as_uint(bf.x), bh1 = __float_as_uint(bf.y);
                uint32_t bl0 = __float_as_uint(bf.z), bl1 = __float_as_uint(bf.w);
                mma_tf32(C[nt], ah0, ah1, ah2, ah3, bl0, bl1);  // hi*lo
                mma_tf32(C[nt], al0, al1, al2, al3, bh0, bh1);  // lo*hi
                mma_tf32(C[nt], ah0, ah1, ah2, ah3, bh0, bh1);  // hi*hi
            }
        }
    }

    int r0 = row0 + wr0 + gid;
    int r1 = r0 + 8;
    #pragma unroll
    for (int nt = 0; nt < 4; nt++) {
        int cidx = nt * 4 + tig;
        if (r0 < N) ((float2*)g_xw)[r0 * 16 + cidx] = make_float2(C[nt].x, C[nt].y);
        if (r1 < N) ((float2*)g_xw)[r1 * 16 + cidx] = make_float2(C[nt].z, C[nt].w);
    }
}

// ---------------- K4: conv1 gather + node finalize + attention + h@W1 --------
__global__ void __launch_bounds__(256) k_conv1node(const float* __restrict__ b0,
                                                   const float* __restrict__ W1, int N) {
    __shared__ float sh[8][128];
    __shared__ float sW1[H0 * H1];
    if (threadIdx.x < H0 * H1) sW1[threadIdx.x] = W1[threadIdx.x];
    __syncthreads();

    int t = blockIdx.x * blockDim.x + threadIdx.x;
    int n = t >> 3;
    if (n >= N) return;
    int lane = threadIdx.x & 31;
    int wid = threadIdx.x >> 5;
    int niw = lane >> 3;
    int j = lane & 7;

    float dc = g_dinv[n];
    int s0 = g_base[n], cnt = g_cnt[n];
    const float4* xw4 = (const float4*)g_xw;
    float4 acc = make_float4(0.f, 0.f, 0.f, 0.f);
    for (int i = 0; i < cnt; i++) {
        int r = g_srow[s0 + i];
        float nr = g_dinv[r] * dc;
        float4 v = xw4[r * 8 + j];
        acc.x = fmaf(nr, v.x, acc.x);
        acc.y = fmaf(nr, v.y, acc.y);
        acc.z = fmaf(nr, v.z, acc.z);
        acc.w = fmaf(nr, v.w, acc.w);
    }
    float4 vs = xw4[n * 8 + j];
    float ds = dc * dc;
    float4 bb = ((const float4*)b0)[j];
    float4 h;
    h.x = acc.x + ds * vs.x + bb.x;
    h.y = acc.y + ds * vs.y + bb.y;
    h.z = acc.z + ds * vs.z + bb.z;
    h.w = acc.w + ds * vs.w + bb.w;

    float4 w1 = ((const float4*)g_wa1)[j];
    float4 w2 = ((const float4*)g_wa2)[j];
    float v1 = h.x * w1.x + h.y * w1.y + h.z * w1.z + h.w * w1.w;
    float v2 = h.x * w2.x + h.y * w2.y + h.z * w2.z + h.w * w2.w;
    #pragma unroll
    for (int o = 1; o < 8; o <<= 1) {
        v1 += __shfl_xor_sync(0xffffffffu, v1, o);
        v2 += __shfl_xor_sync(0xffffffffu, v2, o);
    }
    if (j == 0) { g_a1[n] = v1; g_a2[n] = v2; }

    float* shn = &sh[wid][niw * 32];
    ((float4*)shn)[j] = h;
    __syncwarp();
    float o = 0.f;
    #pragma unroll
    for (int k = 0; k < 32; k++) o = fmaf(shn[k], sW1[k * 8 + j], o);
    g_hw[n * 8 + j] = o;
}

// ---------------- K5: deg2 gather ----------------
__global__ void __launch_bounds__(256) k_deg2(int N) {
    int t = blockIdx.x * blockDim.x + threadIdx.x;
    int n = t >> 2;
    if (n >= N) return;
    int l = t & 3;
    float a2c = g_a2[n] + g_c0;
    int s0 = g_base[n], cnt = g_cnt[n];
    float sum = 0.f;
    for (int i = l; i < cnt; i += 4) {
        int r = g_srow[s0 + i];
        float w = g_a1[r] + a2c;
        if (w > 0.f) {
            float mask = fminf(1.01f / (1.f + __expf(-w)), 1.f);
            sum += mask * w;
        }
    }
    sum += __shfl_xor_sync(0xffffffffu, sum, 1);
    sum += __shfl_xor_sync(0xffffffffu, sum, 2);
    if (l == 0) g_dinv2[n] = rsqrtf(1.f + sum);
}

// ---------------- K6: conv2 gather -> out ----------------
__global__ void __launch_bounds__(256) k_conv2(float* __restrict__ out,
                                               const float* __restrict__ b1, int N) {
    int t = blockIdx.x * blockDim.x + threadIdx.x;
    int n = t >> 1;
    if (n >= N) return;
    int j = t & 1;
    float a2c = g_a2[n] + g_c0;
    float d2n = g_dinv2[n];
    int s0 = g_base[n], cnt = g_cnt[n];
    const float4* hw4 = (const float4*)g_hw;
    float4 acc = make_float4(0.f, 0.f, 0.f, 0.f);
    for (int i = 0; i < cnt; i++) {
        int r = g_srow[s0 + i];
        float w = g_a1[r] + a2c;
        if (w <= 0.f) continue;
        float mask = fminf(1.01f / (1.f + __expf(-w)), 1.f);
        float nr = mask * w * g_dinv2[r];
        float4 v = hw4[r * 2 + j];
        acc.x = fmaf(nr, v.x, acc.x);
        acc.y = fmaf(nr, v.y, acc.y);
        acc.z = fmaf(nr, v.z, acc.z);
        acc.w = fmaf(nr, v.w, acc.w);
    }
    float4 self = hw4[n * 2 + j];
    float4 bb = ((const float4*)b1)[j];
    float4 o;
    o.x = d2n * (acc.x + d2n * self.x) + bb.x;
    o.y = d2n * (acc.y + d2n * self.y) + bb.y;
    o.z = d2n * (acc.z + d2n * self.z) + bb.z;
    o.w = d2n * (acc.w + d2n * self.w) + bb.w;
    ((float4*)out)[n * 2 + j] = o;
}

// ---------------- launch ----------------
extern "C" void kernel_launch(void* const* d_in, const int* in_sizes, int n_in,
                              void* d_out, int out_size) {
    const float* x     = (const float*)d_in[0];
    const void*  eidx  = d_in[1];
    const float* W0    = (const float*)d_in[2];
    const float* b0    = (const float*)d_in[3];
    const float* W1    = (const float*)d_in[4];
    const float* b1    = (const float*)d_in[5];
    const float* Wnb   = (const float*)d_in[6];
    const float* bnb   = (const float*)d_in[7];
    const float* Wself = (const float*)d_in[8];
    const float* bself = (const float*)d_in[9];
    const float* Watt  = (const float*)d_in[10];
    const float* batt  = (const float*)d_in[11];
    float* out = (float*)d_out;

    int N = in_sizes[0] / IN_DIM;
    int E = in_sizes[1] / 2;
    int NB = (N + 1023) / 1024;

    k_init<<<(N + 255) / 256, 256>>>(eidx, Wnb, bnb, Wself, bself, Watt, batt, N);
    k_bfrag<<<32, 256>>>(W0);
    k_convert<<<(E + 255) / 256, 256>>>(eidx, E);
    k_gemm_tc<<<(N + 127) / 128, 256>>>(x, N);
    k_scan1<<<NB, 1024>>>(N);
    k_scan2<<<1, 128>>>(NB);
    k_scan3<<<(N + 255) / 256, 256>>>(N);
    k_scatter<<<(E + 255) / 256, 256>>>(E);
    k_conv1node<<<(N * 8 + 255) / 256, 256>>>(b0, W1, N);
    k_deg2<<<(N * 4 + 255) / 256, 256>>>(N);
    k_conv2<<<(N * 2 + 255) / 256, 256>>>(out, b1, N);
}